// round 6
// baseline (speedup 1.0000x reference)
#include <cuda_runtime.h>
#include <math.h>

#define BATCH  2
#define SEQ    2048
#define DMODEL 1024
#define NHEAD  16
#define DK     64
#define MROWS  (BATCH*SEQ)   // 4096

typedef unsigned long long ull;

// ---- packed fp32x2 helpers (sm_100+ PTX; ptxas never emits these from C++) --
__device__ __forceinline__ ull fma2(ull a, ull b, ull c) {
    ull d;
    asm("fma.rn.f32x2 %0, %1, %2, %3;" : "=l"(d) : "l"(a), "l"(b), "l"(c));
    return d;
}
__device__ __forceinline__ ull mul2(ull a, ull b) {
    ull d;
    asm("mul.rn.f32x2 %0, %1, %2;" : "=l"(d) : "l"(a), "l"(b));
    return d;
}
__device__ __forceinline__ ull dup2(float x) {
    ull d;
    asm("mov.b64 %0, {%1, %1};" : "=l"(d) : "f"(x));
    return d;
}
__device__ __forceinline__ float2 unpack2(ull v) {
    float lo, hi;
    asm("mov.b64 {%0, %1}, %2;" : "=f"(lo), "=f"(hi) : "l"(v));
    return make_float2(lo, hi);
}

// ---------------- scratch (device globals; no allocations allowed) ----------
__device__ float g_q[(size_t)MROWS * DMODEL];   // RoPE'd Q
__device__ float g_k[(size_t)MROWS * DMODEL];   // RoPE'd K
__device__ float g_v[(size_t)MROWS * DMODEL];   // V
__device__ float g_o[(size_t)MROWS * DMODEL];   // attention output
__device__ float g_cos[SEQ * 32];
__device__ float g_sin[SEQ * 32];

// ---------------- RoPE table -------------------------------------------------
__global__ void rope_table_kernel(const int* __restrict__ pos) {
    int idx = blockIdx.x * blockDim.x + threadIdx.x;
    if (idx >= SEQ * 32) return;
    int sp = idx >> 5;
    int i  = idx & 31;
    float p   = (float)pos[sp];
    float inv = powf(10000.0f, -((float)i) / 32.0f);
    float phi = p * inv;
    g_cos[idx] = cosf(phi);
    g_sin[idx] = sinf(phi);
}

// ---------------- SGEMM core: C[m,n] = sum_k A[m,k]*W[n,k]  (NT) -------------
// BM=128, BN=128, BK=16, 256 threads, 8x8 microtile, f32x2-packed along M.
__device__ __forceinline__ void gemm_tile_128x128(
    const float* __restrict__ A, const float* __restrict__ W,
    float* __restrict__ C, bool rope)
{
    __shared__ float As[16][132];   // [k][m]; 132*4=528B rows, 16B-aligned
    __shared__ float Bs[16][132];   // [k][n]

    const int tid = threadIdx.x;
    const int bm0 = blockIdx.y * 128;
    const int bn0 = blockIdx.x * 128;
    const int tm = tid >> 4, tn = tid & 15;
    const int m0 = tm * 8,  n0 = tn * 8;

    // acc2[r2][c] packs rows (m0+2*r2, m0+2*r2+1), column n0+c
    ull acc2[4][8];
#pragma unroll
    for (int r = 0; r < 4; r++)
#pragma unroll
        for (int c = 0; c < 8; c++) acc2[r][c] = 0ull;

    for (int kb = 0; kb < DMODEL; kb += 16) {
        // A tile 128x16 = 512 float4, 2/thread.
        // Map: m = f&127 (warp = 32 consecutive rows, one k-slice) -> STS conflict-free.
#pragma unroll
        for (int t = 0; t < 2; t++) {
            int f  = tid + t * 256;
            int m  = f & 127;
            int k4 = (f >> 7) << 2;
            const float4 av = *(const float4*)(A + (size_t)(bm0 + m) * DMODEL + kb + k4);
            As[k4 + 0][m] = av.x; As[k4 + 1][m] = av.y;
            As[k4 + 2][m] = av.z; As[k4 + 3][m] = av.w;
        }
        // B tile 128x16, same mapping
#pragma unroll
        for (int t = 0; t < 2; t++) {
            int f  = tid + t * 256;
            int n  = f & 127;
            int k4 = (f >> 7) << 2;
            const float4 bv = *(const float4*)(W + (size_t)(bn0 + n) * DMODEL + kb + k4);
            Bs[k4 + 0][n] = bv.x; Bs[k4 + 1][n] = bv.y;
            Bs[k4 + 2][n] = bv.z; Bs[k4 + 3][n] = bv.w;
        }
        __syncthreads();

#pragma unroll
        for (int kk = 0; kk < 16; kk++) {
            // A m-pairs consecutive in smem -> direct 64-bit packed operands
            ulonglong2 a01 = *(const ulonglong2*)(&As[kk][m0]);     // (m0,m0+1),(m0+2,m0+3)
            ulonglong2 a23 = *(const ulonglong2*)(&As[kk][m0 + 4]); // (m0+4..m0+7)
            float4 bl = *(const float4*)(&Bs[kk][n0]);
            float4 bh = *(const float4*)(&Bs[kk][n0 + 4]);
            ull a2[4] = {a01.x, a01.y, a23.x, a23.y};
            ull b2[8] = {dup2(bl.x), dup2(bl.y), dup2(bl.z), dup2(bl.w),
                         dup2(bh.x), dup2(bh.y), dup2(bh.z), dup2(bh.w)};
#pragma unroll
            for (int r = 0; r < 4; r++)
#pragma unroll
                for (int c = 0; c < 8; c++)
                    acc2[r][c] = fma2(a2[r], b2[c], acc2[r][c]);
        }
        __syncthreads();
    }

    // epilogue: unpack + optional fused RoPE + store (2 float4 per row)
#pragma unroll
    for (int r = 0; r < 8; r++) {
        int row = bm0 + m0 + r;
        float rr[8];
#pragma unroll
        for (int c = 0; c < 8; c++) {
            float2 u = unpack2(acc2[r >> 1][c]);
            rr[c] = (r & 1) ? u.y : u.x;
        }
#pragma unroll
        for (int g = 0; g < 2; g++) {
            int col = bn0 + n0 + g * 4;
            float4 o = make_float4(rr[g*4+0], rr[g*4+1], rr[g*4+2], rr[g*4+3]);
            if (rope) {
                int sp = row & (SEQ - 1);
                int i0 = (col & (DK - 1)) >> 1;
                float c0 = g_cos[sp * 32 + i0],     s0 = g_sin[sp * 32 + i0];
                float c1 = g_cos[sp * 32 + i0 + 1], s1 = g_sin[sp * 32 + i0 + 1];
                float e0 = o.x * c0 - o.y * s0;
                float e1 = o.x * s0 + o.y * c0;
                float e2 = o.z * c1 - o.w * s1;
                float e3 = o.z * s1 + o.w * c1;
                o = make_float4(e0, e1, e2, e3);
            }
            *(float4*)(C + (size_t)row * DMODEL + col) = o;
        }
    }
}

__global__ void __launch_bounds__(256) qkv_kernel(
    const float* __restrict__ X,
    const float* __restrict__ Wq, const float* __restrict__ Wk,
    const float* __restrict__ Wv)
{
    const float* W; float* C; bool rope;
    if (blockIdx.z == 0)      { W = Wq; C = g_q; rope = true;  }
    else if (blockIdx.z == 1) { W = Wk; C = g_k; rope = true;  }
    else                      { W = Wv; C = g_v; rope = false; }
    gemm_tile_128x128(X, W, C, rope);
}

__global__ void __launch_bounds__(256) oproj_kernel(
    const float* __restrict__ Wo, float* __restrict__ Out)
{
    gemm_tile_128x128(g_o, Wo, Out, false);
}

// ---------------- causal flash attention, fp32x2, 1 thread = 1 query row ----
__global__ void __launch_bounds__(64) attn_kernel() {
    const int tid = threadIdx.x;
    const int qt = blockIdx.x;
    const int h  = blockIdx.y;
    const int b  = blockIdx.z;
    const int qg = qt * 64 + tid;

    __shared__ float  Qs[64][65];
    __shared__ float4 buf4[512];         // union: K^T [d][j] (64x32) then V [j][d] (32x64)
    __shared__ float  Ps[64][33];
    float* buf = (float*)buf4;

    const float* qbase = g_q + (size_t)(b * SEQ + qt * 64) * DMODEL + h * DK;
#pragma unroll
    for (int it = 0; it < 16; it++) {
        int f  = tid + it * 64;
        int r  = f >> 4;
        int c0 = (f & 15) << 2;
        float4 qv = *(const float4*)(qbase + (size_t)r * DMODEL + c0);
        Qs[r][c0 + 0] = qv.x * 0.125f;
        Qs[r][c0 + 1] = qv.y * 0.125f;
        Qs[r][c0 + 2] = qv.z * 0.125f;
        Qs[r][c0 + 3] = qv.w * 0.125f;
    }

    float m = -1e30f, l = 0.f;
    ull o2[32];                         // packed O: o2[u] = pair (2u, 2u+1)
#pragma unroll
    for (int d = 0; d < 32; d++) o2[d] = 0ull;

    const int ntiles = qt * 2 + 2;
    const int nfull  = qt * 2;
    const float* kbase = g_k + (size_t)(b * SEQ) * DMODEL + h * DK;
    const float* vbase = g_v + (size_t)(b * SEQ) * DMODEL + h * DK;

    for (int kt = 0; kt < ntiles; kt++) {
        const int kg0 = kt * 32;
        __syncthreads();

        // K tile transposed: buf[d][j], conflict-free STS (j = lane)
#pragma unroll
        for (int it = 0; it < 8; it++) {
            int f  = tid + it * 64;
            int j  = f & 31;
            int d0 = (f >> 5) << 2;
            float4 kv = *(const float4*)(kbase + (size_t)(kg0 + j) * DMODEL + d0);
            buf[(d0 + 0) * 32 + j] = kv.x;
            buf[(d0 + 1) * 32 + j] = kv.y;
            buf[(d0 + 2) * 32 + j] = kv.z;
            buf[(d0 + 3) * 32 + j] = kv.w;
        }
        __syncthreads();

        // S = q . k   (packed along j)
        ull s2[16];
#pragma unroll
        for (int j = 0; j < 16; j++) s2[j] = 0ull;
#pragma unroll 8
        for (int d = 0; d < 64; d++) {
            ull qd2 = dup2(Qs[tid][d]);
            const ulonglong2* K2 = (const ulonglong2*)(buf + d * 32);
#pragma unroll
            for (int j4 = 0; j4 < 8; j4++) {
                ulonglong2 kk = K2[j4];
                s2[j4 * 2 + 0] = fma2(qd2, kk.x, s2[j4 * 2 + 0]);
                s2[j4 * 2 + 1] = fma2(qd2, kk.y, s2[j4 * 2 + 1]);
            }
        }
        __syncthreads();   // K readers done before V overwrites buf

        // V tile: buf4[j][d/4]
#pragma unroll
        for (int it = 0; it < 8; it++) {
            int f  = tid + it * 64;
            int j  = f >> 4;
            int d0 = (f & 15) << 2;
            float4 vv = *(const float4*)(vbase + (size_t)(kg0 + j) * DMODEL + d0);
            buf4[j * 16 + (d0 >> 2)] = vv;
        }

        // unpack scores, online softmax (scalar; own row)
        float s[32];
#pragma unroll
        for (int j = 0; j < 16; j++) {
            float2 u = unpack2(s2[j]);
            s[2 * j + 0] = u.x;
            s[2 * j + 1] = u.y;
        }
        if (kt >= nfull) {
#pragma unroll
            for (int j = 0; j < 32; j++)
                if (kg0 + j > qg) s[j] = -1e30f;
        }
        float mn = m;
#pragma unroll
        for (int j = 0; j < 32; j++) mn = fmaxf(mn, s[j]);
        float alpha = __expf(m - mn);
        m = mn;
        float ps = 0.f;
#pragma unroll
        for (int j = 0; j < 32; j++) {
            float p = __expf(s[j] - mn);
            Ps[tid][j] = p;
            ps += p;
        }
        l = l * alpha + ps;
        ull alpha2 = dup2(alpha);
#pragma unroll
        for (int d = 0; d < 32; d++) o2[d] = mul2(alpha2, o2[d]);

        __syncthreads();   // V tile visible

        // O += P * V  (V2[u] covers floats 4u..4u+3; .x->o2[2u], .y->o2[2u+1])
#pragma unroll 4
        for (int j = 0; j < 32; j++) {
            ull pj2 = dup2(Ps[tid][j]);
            const ulonglong2* V2 = (const ulonglong2*)(buf4 + j * 16);
#pragma unroll
            for (int u = 0; u < 16; u++) {
                ulonglong2 vv = V2[u];
                o2[2 * u + 0] = fma2(pj2, vv.x, o2[2 * u + 0]);
                o2[2 * u + 1] = fma2(pj2, vv.y, o2[2 * u + 1]);
            }
        }
    }

    // normalize + store
    ull inv2 = dup2(1.f / l);
    float* obase = g_o + (size_t)(b * SEQ + qg) * DMODEL + h * DK;
#pragma unroll
    for (int d4 = 0; d4 < 16; d4++) {
        float2 u0 = unpack2(mul2(inv2, o2[d4 * 2 + 0]));
        float2 u1 = unpack2(mul2(inv2, o2[d4 * 2 + 1]));
        *(float4*)(obase + d4 * 4) = make_float4(u0.x, u0.y, u1.x, u1.y);
    }
}

// ---------------- launch -----------------------------------------------------
extern "C" void kernel_launch(void* const* d_in, const int* in_sizes, int n_in,
                              void* d_out, int out_size) {
    (void)in_sizes; (void)n_in; (void)out_size;
    const float* x   = (const float*)d_in[0];
    const float* Wq  = (const float*)d_in[1];
    const float* Wk  = (const float*)d_in[2];
    const float* Wv  = (const float*)d_in[3];
    const float* Wo  = (const float*)d_in[4];
    const int*   pos = (const int*)  d_in[5];

    rope_table_kernel<<<(SEQ * 32 + 255) / 256, 256>>>(pos);

    dim3 gq(DMODEL / 128, MROWS / 128, 3);
    qkv_kernel<<<gq, 256>>>(x, Wq, Wk, Wv);

    dim3 ga(SEQ / 64, NHEAD, BATCH);
    attn_kernel<<<ga, 64>>>();

    dim3 go(DMODEL / 128, MROWS / 128, 1);
    oproj_kernel<<<go, 256>>>(Wo, (float*)d_out);
}

// round 10
// speedup vs baseline: 1.2482x; 1.2482x over previous
#include <cuda_runtime.h>
#include <math.h>
#include <stdint.h>

#define BATCH  2
#define SEQ    2048
#define DMODEL 1024
#define NHEAD  16
#define DK     64
#define MROWS  (BATCH*SEQ)   // 4096

typedef unsigned long long ull;

// ---- packed fp32x2 helpers (attention) --------------------------------------
__device__ __forceinline__ ull fma2(ull a, ull b, ull c) {
    ull d; asm("fma.rn.f32x2 %0, %1, %2, %3;" : "=l"(d) : "l"(a), "l"(b), "l"(c)); return d;
}
__device__ __forceinline__ ull mul2(ull a, ull b) {
    ull d; asm("mul.rn.f32x2 %0, %1, %2;" : "=l"(d) : "l"(a), "l"(b)); return d;
}
__device__ __forceinline__ ull dup2(float x) {
    ull d; asm("mov.b64 %0, {%1, %1};" : "=l"(d) : "f"(x)); return d;
}
__device__ __forceinline__ float2 unpack2(ull v) {
    float lo, hi; asm("mov.b64 {%0, %1}, %2;" : "=f"(lo), "=f"(hi) : "l"(v));
    return make_float2(lo, hi);
}

// ---- tf32 helpers -----------------------------------------------------------
__device__ __forceinline__ uint32_t to_tf32(float f) {
    uint32_t r; asm("cvt.rna.tf32.f32 %0, %1;" : "=r"(r) : "f"(f)); return r;
}
__device__ __forceinline__ void mma_tf32(float& c0, float& c1, float& c2, float& c3,
                                         uint32_t a0, uint32_t a1, uint32_t a2, uint32_t a3,
                                         uint32_t b0, uint32_t b1) {
    asm volatile("mma.sync.aligned.m16n8k8.row.col.f32.tf32.tf32.f32 "
        "{%0,%1,%2,%3}, {%4,%5,%6,%7}, {%8,%9}, {%0,%1,%2,%3};"
        : "+f"(c0), "+f"(c1), "+f"(c2), "+f"(c3)
        : "r"(a0), "r"(a1), "r"(a2), "r"(a3), "r"(b0), "r"(b1));
}

// ---------------- scratch (device globals; no allocations allowed) ----------
__device__ float g_q[(size_t)MROWS * DMODEL];
__device__ float g_k[(size_t)MROWS * DMODEL];
__device__ float g_v[(size_t)MROWS * DMODEL];
__device__ float g_o[(size_t)MROWS * DMODEL];
__device__ float g_cos[SEQ * 32];
__device__ float g_sin[SEQ * 32];

// ---------------- RoPE table -------------------------------------------------
__global__ void rope_table_kernel(const int* __restrict__ pos) {
    int idx = blockIdx.x * blockDim.x + threadIdx.x;
    if (idx >= SEQ * 32) return;
    int sp = idx >> 5;
    int i  = idx & 31;
    float p   = (float)pos[sp];
    float inv = powf(10000.0f, -((float)i) / 32.0f);
    float phi = p * inv;
    g_cos[idx] = cosf(phi);
    g_sin[idx] = sinf(phi);
}

// ---------------- tf32 mma.sync GEMM: C[m,n] = sum_k A[m,k]*W[n,k] (NT) ------
// BM=128, BN=64, BK=16, 256 threads (8 warps), warp tile 32x32 (2 x 4 atoms).
// smem strides: 136 % 32 == 72 % 32 == 8 -> fragment LDS banks = 8*t4+g,
// all 32 distinct -> conflict-free. STS (32 consecutive m, fixed k) also CF.
__device__ __forceinline__ void gemm_mma_tile(
    const float* __restrict__ A, const float* __restrict__ W,
    float* __restrict__ C, bool rope)
{
    __shared__ uint32_t As[16][136];   // tf32 bits, [k][m]
    __shared__ uint32_t Bs[16][72];    // tf32 bits, [k][n]

    const int tid  = threadIdx.x;
    const int wid  = tid >> 5;
    const int lane = tid & 31;
    const int g    = lane >> 2;        // group id (0..7)
    const int t4   = lane & 3;         // thread-in-group
    const int bm0  = blockIdx.y * 128;
    const int bn0  = blockIdx.x * 64;
    const int rb   = (wid & 3) * 32;   // warp row base in tile
    const int cb   = (wid >> 2) * 32;  // warp col base in tile

    float c[2][4][4];
#pragma unroll
    for (int i = 0; i < 2; i++)
#pragma unroll
        for (int j = 0; j < 4; j++)
#pragma unroll
            for (int q = 0; q < 4; q++) c[i][j][q] = 0.f;

    // global-load index maps (conflict-free STS)
    const int am_ld  = tid & 127;             // A: row
    const int ak4_ld = (tid >> 7) << 2;       // A: k4 base for t=0 (0/4); t=1 adds 8
    const int bn_ld  = tid & 63;              // B: row (n)
    const int bk4_ld = (tid >> 6) << 2;       // B: k4 (0/4/8/12)

    const float* Ab = A + (size_t)(bm0 + am_ld) * DMODEL + ak4_ld;
    const float* Wb = W + (size_t)(bn0 + bn_ld) * DMODEL + bk4_ld;

    float4 pa0 = *(const float4*)(Ab);
    float4 pa1 = *(const float4*)(Ab + 8);
    float4 pb  = *(const float4*)(Wb);

#pragma unroll 1
    for (int s = 0; s < DMODEL / 16; s++) {
        // STS (convert to tf32 bits)
        As[ak4_ld + 0][am_ld] = to_tf32(pa0.x);
        As[ak4_ld + 1][am_ld] = to_tf32(pa0.y);
        As[ak4_ld + 2][am_ld] = to_tf32(pa0.z);
        As[ak4_ld + 3][am_ld] = to_tf32(pa0.w);
        As[ak4_ld + 8][am_ld] = to_tf32(pa1.x);
        As[ak4_ld + 9][am_ld] = to_tf32(pa1.y);
        As[ak4_ld +10][am_ld] = to_tf32(pa1.z);
        As[ak4_ld +11][am_ld] = to_tf32(pa1.w);
        Bs[bk4_ld + 0][bn_ld] = to_tf32(pb.x);
        Bs[bk4_ld + 1][bn_ld] = to_tf32(pb.y);
        Bs[bk4_ld + 2][bn_ld] = to_tf32(pb.z);
        Bs[bk4_ld + 3][bn_ld] = to_tf32(pb.w);
        __syncthreads();

        // prefetch next k-slab while computing this one
        if (s + 1 < DMODEL / 16) {
            pa0 = *(const float4*)(Ab + (s + 1) * 16);
            pa1 = *(const float4*)(Ab + (s + 1) * 16 + 8);
            pb  = *(const float4*)(Wb + (s + 1) * 16);
        }

#pragma unroll
        for (int ks = 0; ks < 16; ks += 8) {
            uint32_t a[2][4], b[4][2];
#pragma unroll
            for (int am = 0; am < 2; am++) {
                int m = rb + am * 16 + g;
                a[am][0] = As[ks + t4    ][m];
                a[am][1] = As[ks + t4    ][m + 8];
                a[am][2] = As[ks + t4 + 4][m];
                a[am][3] = As[ks + t4 + 4][m + 8];
            }
#pragma unroll
            for (int an = 0; an < 4; an++) {
                int n = cb + an * 8 + g;
                b[an][0] = Bs[ks + t4    ][n];
                b[an][1] = Bs[ks + t4 + 4][n];
            }
#pragma unroll
            for (int am = 0; am < 2; am++)
#pragma unroll
                for (int an = 0; an < 4; an++)
                    mma_tf32(c[am][an][0], c[am][an][1], c[am][an][2], c[am][an][3],
                             a[am][0], a[am][1], a[am][2], a[am][3],
                             b[an][0], b[an][1]);
        }
        __syncthreads();
    }

    // epilogue: c0,c1 -> (row, col..col+1); c2,c3 -> (row+8, ...). Fused RoPE.
#pragma unroll
    for (int am = 0; am < 2; am++) {
#pragma unroll
        for (int an = 0; an < 4; an++) {
            int col = bn0 + cb + an * 8 + t4 * 2;
            int r0  = bm0 + rb + am * 16 + g;
            int r1  = r0 + 8;
            float e0 = c[am][an][0], e1 = c[am][an][1];
            float e2 = c[am][an][2], e3 = c[am][an][3];
            if (rope) {
                int i0 = (col & (DK - 1)) >> 1;
                int sp0 = r0 & (SEQ - 1), sp1 = r1 & (SEQ - 1);
                float cc0 = g_cos[sp0 * 32 + i0], ss0 = g_sin[sp0 * 32 + i0];
                float cc1 = g_cos[sp1 * 32 + i0], ss1 = g_sin[sp1 * 32 + i0];
                float x0 = e0, y0 = e1, x1 = e2, y1 = e3;
                e0 = x0 * cc0 - y0 * ss0;  e1 = x0 * ss0 + y0 * cc0;
                e2 = x1 * cc1 - y1 * ss1;  e3 = x1 * ss1 + y1 * cc1;
            }
            *(float2*)(C + (size_t)r0 * DMODEL + col) = make_float2(e0, e1);
            *(float2*)(C + (size_t)r1 * DMODEL + col) = make_float2(e2, e3);
        }
    }
}

__global__ void __launch_bounds__(256) qkv_kernel(
    const float* __restrict__ X,
    const float* __restrict__ Wq, const float* __restrict__ Wk,
    const float* __restrict__ Wv)
{
    const float* W; float* C; bool rope;
    if (blockIdx.z == 0)      { W = Wq; C = g_q; rope = true;  }
    else if (blockIdx.z == 1) { W = Wk; C = g_k; rope = true;  }
    else                      { W = Wv; C = g_v; rope = false; }
    gemm_mma_tile(X, W, C, rope);
}

__global__ void __launch_bounds__(256) oproj_kernel(
    const float* __restrict__ Wo, float* __restrict__ Out)
{
    gemm_mma_tile(g_o, Wo, Out, false);
}

// ---------------- causal flash attention, fp32x2 (unchanged from R5) --------
__global__ void __launch_bounds__(64) attn_kernel() {
    const int tid = threadIdx.x;
    const int qt = blockIdx.x;
    const int h  = blockIdx.y;
    const int b  = blockIdx.z;
    const int qg = qt * 64 + tid;

    __shared__ float  Qs[64][65];
    __shared__ float4 buf4[512];
    __shared__ float  Ps[64][33];
    float* buf = (float*)buf4;

    const float* qbase = g_q + (size_t)(b * SEQ + qt * 64) * DMODEL + h * DK;
#pragma unroll
    for (int it = 0; it < 16; it++) {
        int f  = tid + it * 64;
        int r  = f >> 4;
        int c0 = (f & 15) << 2;
        float4 qv = *(const float4*)(qbase + (size_t)r * DMODEL + c0);
        Qs[r][c0 + 0] = qv.x * 0.125f;
        Qs[r][c0 + 1] = qv.y * 0.125f;
        Qs[r][c0 + 2] = qv.z * 0.125f;
        Qs[r][c0 + 3] = qv.w * 0.125f;
    }

    float m = -1e30f, l = 0.f;
    ull o2[32];
#pragma unroll
    for (int d = 0; d < 32; d++) o2[d] = 0ull;

    const int ntiles = qt * 2 + 2;
    const int nfull  = qt * 2;
    const float* kbase = g_k + (size_t)(b * SEQ) * DMODEL + h * DK;
    const float* vbase = g_v + (size_t)(b * SEQ) * DMODEL + h * DK;

    for (int kt = 0; kt < ntiles; kt++) {
        const int kg0 = kt * 32;
        __syncthreads();

#pragma unroll
        for (int it = 0; it < 8; it++) {
            int f  = tid + it * 64;
            int j  = f & 31;
            int d0 = (f >> 5) << 2;
            float4 kv = *(const float4*)(kbase + (size_t)(kg0 + j) * DMODEL + d0);
            buf[(d0 + 0) * 32 + j] = kv.x;
            buf[(d0 + 1) * 32 + j] = kv.y;
            buf[(d0 + 2) * 32 + j] = kv.z;
            buf[(d0 + 3) * 32 + j] = kv.w;
        }
        __syncthreads();

        ull s2[16];
#pragma unroll
        for (int j = 0; j < 16; j++) s2[j] = 0ull;
#pragma unroll 8
        for (int d = 0; d < 64; d++) {
            ull qd2 = dup2(Qs[tid][d]);
            const ulonglong2* K2 = (const ulonglong2*)(buf + d * 32);
#pragma unroll
            for (int j4 = 0; j4 < 8; j4++) {
                ulonglong2 kk = K2[j4];
                s2[j4 * 2 + 0] = fma2(qd2, kk.x, s2[j4 * 2 + 0]);
                s2[j4 * 2 + 1] = fma2(qd2, kk.y, s2[j4 * 2 + 1]);
            }
        }
        __syncthreads();

#pragma unroll
        for (int it = 0; it < 8; it++) {
            int f  = tid + it * 64;
            int j  = f >> 4;
            int d0 = (f & 15) << 2;
            float4 vv = *(const float4*)(vbase + (size_t)(kg0 + j) * DMODEL + d0);
            buf4[j * 16 + (d0 >> 2)] = vv;
        }

        float s[32];
#pragma unroll
        for (int j = 0; j < 16; j++) {
            float2 u = unpack2(s2[j]);
            s[2 * j + 0] = u.x;
            s[2 * j + 1] = u.y;
        }
        if (kt >= nfull) {
#pragma unroll
            for (int j = 0; j < 32; j++)
                if (kg0 + j > qg) s[j] = -1e30f;
        }
        float mn = m;
#pragma unroll
        for (int j = 0; j < 32; j++) mn = fmaxf(mn, s[j]);
        float alpha = __expf(m - mn);
        m = mn;
        float ps = 0.f;
#pragma unroll
        for (int j = 0; j < 32; j++) {
            float p = __expf(s[j] - mn);
            Ps[tid][j] = p;
            ps += p;
        }
        l = l * alpha + ps;
        ull alpha2 = dup2(alpha);
#pragma unroll
        for (int d = 0; d < 32; d++) o2[d] = mul2(alpha2, o2[d]);

        __syncthreads();

#pragma unroll 4
        for (int j = 0; j < 32; j++) {
            ull pj2 = dup2(Ps[tid][j]);
            const ulonglong2* V2 = (const ulonglong2*)(buf4 + j * 16);
#pragma unroll
            for (int u = 0; u < 16; u++) {
                ulonglong2 vv = V2[u];
                o2[2 * u + 0] = fma2(pj2, vv.x, o2[2 * u + 0]);
                o2[2 * u + 1] = fma2(pj2, vv.y, o2[2 * u + 1]);
            }
        }
    }

    ull inv2 = dup2(1.f / l);
    float* obase = g_o + (size_t)(b * SEQ + qg) * DMODEL + h * DK;
#pragma unroll
    for (int d4 = 0; d4 < 16; d4++) {
        float2 u0 = unpack2(mul2(inv2, o2[d4 * 2 + 0]));
        float2 u1 = unpack2(mul2(inv2, o2[d4 * 2 + 1]));
        *(float4*)(obase + d4 * 4) = make_float4(u0.x, u0.y, u1.x, u1.y);
    }
}

// ---------------- launch -----------------------------------------------------
extern "C" void kernel_launch(void* const* d_in, const int* in_sizes, int n_in,
                              void* d_out, int out_size) {
    (void)in_sizes; (void)n_in; (void)out_size;
    const float* x   = (const float*)d_in[0];
    const float* Wq  = (const float*)d_in[1];
    const float* Wk  = (const float*)d_in[2];
    const float* Wv  = (const float*)d_in[3];
    const float* Wo  = (const float*)d_in[4];
    const int*   pos = (const int*)  d_in[5];

    rope_table_kernel<<<(SEQ * 32 + 255) / 256, 256>>>(pos);

    dim3 gq(DMODEL / 64, MROWS / 128, 3);
    qkv_kernel<<<gq, 256>>>(x, Wq, Wk, Wv);

    dim3 ga(SEQ / 64, NHEAD, BATCH);
    attn_kernel<<<ga, 64>>>();

    dim3 go(DMODEL / 64, MROWS / 128, 1);
    oproj_kernel<<<go, 256>>>(Wo, (float*)d_out);
}

// round 12
// speedup vs baseline: 2.1240x; 1.7017x over previous
#include <cuda_runtime.h>
#include <math.h>
#include <stdint.h>

#define BATCH  2
#define SEQ    2048
#define DMODEL 1024
#define NHEAD  16
#define DK     64
#define MROWS  (BATCH*SEQ)   // 4096

// ---- tf32 helpers -----------------------------------------------------------
__device__ __forceinline__ uint32_t to_tf32(float f) {
    uint32_t r; asm("cvt.rna.tf32.f32 %0, %1;" : "=r"(r) : "f"(f)); return r;
}
__device__ __forceinline__ void mma_tf32(float& c0, float& c1, float& c2, float& c3,
                                         uint32_t a0, uint32_t a1, uint32_t a2, uint32_t a3,
                                         uint32_t b0, uint32_t b1) {
    asm volatile("mma.sync.aligned.m16n8k8.row.col.f32.tf32.tf32.f32 "
        "{%0,%1,%2,%3}, {%4,%5,%6,%7}, {%8,%9}, {%0,%1,%2,%3};"
        : "+f"(c0), "+f"(c1), "+f"(c2), "+f"(c3)
        : "r"(a0), "r"(a1), "r"(a2), "r"(a3), "r"(b0), "r"(b1));
}

// ---------------- scratch (device globals; no allocations allowed) ----------
__device__ float g_q[(size_t)MROWS * DMODEL];
__device__ float g_k[(size_t)MROWS * DMODEL];
__device__ float g_v[(size_t)MROWS * DMODEL];
__device__ float g_o[(size_t)MROWS * DMODEL];
__device__ float g_cos[SEQ * 32];
__device__ float g_sin[SEQ * 32];

// ---------------- RoPE table -------------------------------------------------
__global__ void rope_table_kernel(const int* __restrict__ pos) {
    int idx = blockIdx.x * blockDim.x + threadIdx.x;
    if (idx >= SEQ * 32) return;
    int sp = idx >> 5;
    int i  = idx & 31;
    float p   = (float)pos[sp];
    float inv = powf(10000.0f, -((float)i) / 32.0f);
    float phi = p * inv;
    g_cos[idx] = cosf(phi);
    g_sin[idx] = sinf(phi);
}

// ---------------- tf32 mma GEMM, 2-stage double buffer -----------------------
// C[m,n] = sum_k A[m,k]*W[n,k]; BM=128 BN=64 BK=16; 8 warps, warp tile 32x32.
__device__ __forceinline__ void gemm_mma_tile(
    const float* __restrict__ A, const float* __restrict__ W,
    float* __restrict__ C, bool rope)
{
    __shared__ uint32_t As[2][16][136];
    __shared__ uint32_t Bs[2][16][72];

    const int tid  = threadIdx.x;
    const int wid  = tid >> 5;
    const int lane = tid & 31;
    const int g    = lane >> 2;
    const int t4   = lane & 3;
    const int bm0  = blockIdx.y * 128;
    const int bn0  = blockIdx.x * 64;
    const int rb   = (wid & 3) * 32;
    const int cb   = (wid >> 2) * 32;

    float c[2][4][4];
#pragma unroll
    for (int i = 0; i < 2; i++)
#pragma unroll
        for (int j = 0; j < 4; j++)
#pragma unroll
            for (int q = 0; q < 4; q++) c[i][j][q] = 0.f;

    const int am_ld  = tid & 127;
    const int ak4_ld = (tid >> 7) << 2;
    const int bn_ld  = tid & 63;
    const int bk4_ld = (tid >> 6) << 2;

    const float* Ab = A + (size_t)(bm0 + am_ld) * DMODEL + ak4_ld;
    const float* Wb = W + (size_t)(bn0 + bn_ld) * DMODEL + bk4_ld;

    float4 pa0, pa1, pb;

#define GEMM_LDG(s) do { \
        pa0 = *(const float4*)(Ab + (s) * 16); \
        pa1 = *(const float4*)(Ab + (s) * 16 + 8); \
        pb  = *(const float4*)(Wb + (s) * 16); \
    } while (0)

#define GEMM_STS(bf) do { \
        As[bf][ak4_ld + 0][am_ld] = to_tf32(pa0.x); \
        As[bf][ak4_ld + 1][am_ld] = to_tf32(pa0.y); \
        As[bf][ak4_ld + 2][am_ld] = to_tf32(pa0.z); \
        As[bf][ak4_ld + 3][am_ld] = to_tf32(pa0.w); \
        As[bf][ak4_ld + 8][am_ld] = to_tf32(pa1.x); \
        As[bf][ak4_ld + 9][am_ld] = to_tf32(pa1.y); \
        As[bf][ak4_ld +10][am_ld] = to_tf32(pa1.z); \
        As[bf][ak4_ld +11][am_ld] = to_tf32(pa1.w); \
        Bs[bf][bk4_ld + 0][bn_ld] = to_tf32(pb.x); \
        Bs[bf][bk4_ld + 1][bn_ld] = to_tf32(pb.y); \
        Bs[bf][bk4_ld + 2][bn_ld] = to_tf32(pb.z); \
        Bs[bf][bk4_ld + 3][bn_ld] = to_tf32(pb.w); \
    } while (0)

    GEMM_LDG(0);
    GEMM_STS(0);
    GEMM_LDG(1);

#pragma unroll 1
    for (int s = 0; s < DMODEL / 16; s++) {
        __syncthreads();                 // buf[s&1] ready; buf[(s+1)&1] free
        const int cur = s & 1;
        if (s + 1 < DMODEL / 16) GEMM_STS(cur ^ 1);
        if (s + 2 < DMODEL / 16) GEMM_LDG(s + 2);

#pragma unroll
        for (int ks = 0; ks < 16; ks += 8) {
            uint32_t a[2][4], bfr[4][2];
#pragma unroll
            for (int am = 0; am < 2; am++) {
                int m = rb + am * 16 + g;
                a[am][0] = As[cur][ks + t4    ][m];
                a[am][1] = As[cur][ks + t4    ][m + 8];
                a[am][2] = As[cur][ks + t4 + 4][m];
                a[am][3] = As[cur][ks + t4 + 4][m + 8];
            }
#pragma unroll
            for (int an = 0; an < 4; an++) {
                int n = cb + an * 8 + g;
                bfr[an][0] = Bs[cur][ks + t4    ][n];
                bfr[an][1] = Bs[cur][ks + t4 + 4][n];
            }
#pragma unroll
            for (int am = 0; am < 2; am++)
#pragma unroll
                for (int an = 0; an < 4; an++)
                    mma_tf32(c[am][an][0], c[am][an][1], c[am][an][2], c[am][an][3],
                             a[am][0], a[am][1], a[am][2], a[am][3],
                             bfr[an][0], bfr[an][1]);
        }
    }
#undef GEMM_LDG
#undef GEMM_STS

    // epilogue with fused RoPE
#pragma unroll
    for (int am = 0; am < 2; am++) {
#pragma unroll
        for (int an = 0; an < 4; an++) {
            int col = bn0 + cb + an * 8 + t4 * 2;
            int r0  = bm0 + rb + am * 16 + g;
            int r1  = r0 + 8;
            float e0 = c[am][an][0], e1 = c[am][an][1];
            float e2 = c[am][an][2], e3 = c[am][an][3];
            if (rope) {
                int i0 = (col & (DK - 1)) >> 1;
                int sp0 = r0 & (SEQ - 1), sp1 = r1 & (SEQ - 1);
                float cc0 = g_cos[sp0 * 32 + i0], ss0 = g_sin[sp0 * 32 + i0];
                float cc1 = g_cos[sp1 * 32 + i0], ss1 = g_sin[sp1 * 32 + i0];
                float x0 = e0, y0 = e1, x1 = e2, y1 = e3;
                e0 = x0 * cc0 - y0 * ss0;  e1 = x0 * ss0 + y0 * cc0;
                e2 = x1 * cc1 - y1 * ss1;  e3 = x1 * ss1 + y1 * cc1;
            }
            *(float2*)(C + (size_t)r0 * DMODEL + col) = make_float2(e0, e1);
            *(float2*)(C + (size_t)r1 * DMODEL + col) = make_float2(e2, e3);
        }
    }
}

__global__ void __launch_bounds__(256) qkv_kernel(
    const float* __restrict__ X,
    const float* __restrict__ Wq, const float* __restrict__ Wk,
    const float* __restrict__ Wv)
{
    const float* W; float* C; bool rope;
    if (blockIdx.z == 0)      { W = Wq; C = g_q; rope = true;  }
    else if (blockIdx.z == 1) { W = Wk; C = g_k; rope = true;  }
    else                      { W = Wv; C = g_v; rope = false; }
    gemm_mma_tile(X, W, C, rope);
}

__global__ void __launch_bounds__(256) oproj_kernel(
    const float* __restrict__ Wo, float* __restrict__ Out)
{
    gemm_mma_tile(g_o, Wo, Out, false);
}

// ---------------- tensor-core causal flash attention -------------------------
// 64 q-rows x 64 keys per tile; 128 threads (4 warps, warp = 16 q-rows).
// S = Q@K^T and O += P@V via m16n8k8 tf32; softmax fp32 with quad shuffles.
// smem layouts (stride mod 32 == 4 -> fragment LDS banks 4g+t4, CF):
//   Qs[q][d] 64x68, Ks[j][d] 64x68, Ps[q][j] 64x68, Vs[j][d] 64x72 (8t4+g CF).
#define QS_OFF 0
#define KS_OFF 17408
#define PS_OFF 34816
#define VS_OFF 52224
#define ATTN_SMEM 70656

__global__ void __launch_bounds__(128) attn_kernel() {
    extern __shared__ char smc[];
    uint32_t* Qs = (uint32_t*)(smc + QS_OFF);
    uint32_t* Ks = (uint32_t*)(smc + KS_OFF);
    uint32_t* Ps = (uint32_t*)(smc + PS_OFF);
    uint32_t* Vs = (uint32_t*)(smc + VS_OFF);

    const int tid  = threadIdx.x;
    const int wid  = tid >> 5;
    const int lane = tid & 31;
    const int g    = lane >> 2;
    const int t4   = lane & 3;
    const int qt = blockIdx.x, h = blockIdx.y, b = blockIdx.z;
    const int rw = wid * 16;            // warp's q-row base (local)

    // load Q tile (pre-scaled by exact 0.125), convert tf32
    const float* qbase = g_q + (size_t)(b * SEQ + qt * 64) * DMODEL + h * DK;
#pragma unroll
    for (int it = 0; it < 8; it++) {
        int f  = tid + it * 128;
        int r  = f >> 4;
        int d0 = (f & 15) << 2;
        float4 qv = *(const float4*)(qbase + (size_t)r * DMODEL + d0);
        Qs[r * 68 + d0 + 0] = to_tf32(qv.x * 0.125f);
        Qs[r * 68 + d0 + 1] = to_tf32(qv.y * 0.125f);
        Qs[r * 68 + d0 + 2] = to_tf32(qv.z * 0.125f);
        Qs[r * 68 + d0 + 3] = to_tf32(qv.w * 0.125f);
    }

    float m0 = -1e30f, m1 = -1e30f, l0 = 0.f, l1 = 0.f;
    float o[8][4];
#pragma unroll
    for (int an = 0; an < 8; an++)
#pragma unroll
        for (int q = 0; q < 4; q++) o[an][q] = 0.f;

    const float* kbase = g_k + (size_t)(b * SEQ) * DMODEL + h * DK;
    const float* vbase = g_v + (size_t)(b * SEQ) * DMODEL + h * DK;

#pragma unroll 1
    for (int kt = 0; kt <= qt; kt++) {
        __syncthreads();                 // prior PV readers done with Ks/Vs/Ps

        // load K and V tiles (tf32)
#pragma unroll
        for (int it = 0; it < 8; it++) {
            int f  = tid + it * 128;
            int j  = f >> 4;
            int d0 = (f & 15) << 2;
            const float* kr = kbase + (size_t)(kt * 64 + j) * DMODEL + d0;
            float4 kv = *(const float4*)kr;
            Ks[j * 68 + d0 + 0] = to_tf32(kv.x);
            Ks[j * 68 + d0 + 1] = to_tf32(kv.y);
            Ks[j * 68 + d0 + 2] = to_tf32(kv.z);
            Ks[j * 68 + d0 + 3] = to_tf32(kv.w);
            const float* vr = vbase + (size_t)(kt * 64 + j) * DMODEL + d0;
            float4 vv = *(const float4*)vr;
            Vs[j * 72 + d0 + 0] = to_tf32(vv.x);
            Vs[j * 72 + d0 + 1] = to_tf32(vv.y);
            Vs[j * 72 + d0 + 2] = to_tf32(vv.z);
            Vs[j * 72 + d0 + 3] = to_tf32(vv.w);
        }
        __syncthreads();

        // S = Q @ K^T   (warp: 16 rows x 64 cols = 1 m-atom x 8 n-atoms)
        float sc[8][4];
#pragma unroll
        for (int an = 0; an < 8; an++)
#pragma unroll
            for (int q = 0; q < 4; q++) sc[an][q] = 0.f;
#pragma unroll
        for (int ks = 0; ks < 64; ks += 8) {
            uint32_t a0 = Qs[(rw + g)     * 68 + ks + t4];
            uint32_t a1 = Qs[(rw + g + 8) * 68 + ks + t4];
            uint32_t a2 = Qs[(rw + g)     * 68 + ks + t4 + 4];
            uint32_t a3 = Qs[(rw + g + 8) * 68 + ks + t4 + 4];
#pragma unroll
            for (int an = 0; an < 8; an++) {
                uint32_t b0 = Ks[(an * 8 + g) * 68 + ks + t4];
                uint32_t b1 = Ks[(an * 8 + g) * 68 + ks + t4 + 4];
                mma_tf32(sc[an][0], sc[an][1], sc[an][2], sc[an][3],
                         a0, a1, a2, a3, b0, b1);
            }
        }

        // causal mask (diagonal tile only; offsets cancel -> compare local idx)
        if (kt == qt) {
            int q0 = rw + g, q1 = q0 + 8;
#pragma unroll
            for (int an = 0; an < 8; an++) {
                int c0 = an * 8 + t4 * 2;
                if (c0     > q0) sc[an][0] = -1e30f;
                if (c0 + 1 > q0) sc[an][1] = -1e30f;
                if (c0     > q1) sc[an][2] = -1e30f;
                if (c0 + 1 > q1) sc[an][3] = -1e30f;
            }
        }

        // online softmax (rows rw+g and rw+g+8; quad reduction over t4)
        float mx0 = -1e30f, mx1 = -1e30f;
#pragma unroll
        for (int an = 0; an < 8; an++) {
            mx0 = fmaxf(mx0, fmaxf(sc[an][0], sc[an][1]));
            mx1 = fmaxf(mx1, fmaxf(sc[an][2], sc[an][3]));
        }
        mx0 = fmaxf(mx0, __shfl_xor_sync(0xffffffffu, mx0, 1));
        mx0 = fmaxf(mx0, __shfl_xor_sync(0xffffffffu, mx0, 2));
        mx1 = fmaxf(mx1, __shfl_xor_sync(0xffffffffu, mx1, 1));
        mx1 = fmaxf(mx1, __shfl_xor_sync(0xffffffffu, mx1, 2));
        float nm0 = fmaxf(m0, mx0), nm1 = fmaxf(m1, mx1);
        float al0 = __expf(m0 - nm0), al1 = __expf(m1 - nm1);
        m0 = nm0; m1 = nm1;

        float sum0 = 0.f, sum1 = 0.f;
#pragma unroll
        for (int an = 0; an < 8; an++) {
            float p0 = __expf(sc[an][0] - nm0);
            float p1 = __expf(sc[an][1] - nm0);
            float p2 = __expf(sc[an][2] - nm1);
            float p3 = __expf(sc[an][3] - nm1);
            sum0 += p0 + p1;
            sum1 += p2 + p3;
            int c0 = an * 8 + t4 * 2;
            Ps[(rw + g)     * 68 + c0    ] = to_tf32(p0);
            Ps[(rw + g)     * 68 + c0 + 1] = to_tf32(p1);
            Ps[(rw + g + 8) * 68 + c0    ] = to_tf32(p2);
            Ps[(rw + g + 8) * 68 + c0 + 1] = to_tf32(p3);
        }
        sum0 += __shfl_xor_sync(0xffffffffu, sum0, 1);
        sum0 += __shfl_xor_sync(0xffffffffu, sum0, 2);
        sum1 += __shfl_xor_sync(0xffffffffu, sum1, 1);
        sum1 += __shfl_xor_sync(0xffffffffu, sum1, 2);
        l0 = l0 * al0 + sum0;
        l1 = l1 * al1 + sum1;

#pragma unroll
        for (int an = 0; an < 8; an++) {
            o[an][0] *= al0; o[an][1] *= al0;
            o[an][2] *= al1; o[an][3] *= al1;
        }

        __syncthreads();                 // Ps visible to the whole warp quad set

        // O += P @ V   (A = Ps[q][j], B = Vs[j][d] -> direct b-fragment)
#pragma unroll
        for (int ks = 0; ks < 64; ks += 8) {
            uint32_t a0 = Ps[(rw + g)     * 68 + ks + t4];
            uint32_t a1 = Ps[(rw + g + 8) * 68 + ks + t4];
            uint32_t a2 = Ps[(rw + g)     * 68 + ks + t4 + 4];
            uint32_t a3 = Ps[(rw + g + 8) * 68 + ks + t4 + 4];
#pragma unroll
            for (int an = 0; an < 8; an++) {
                uint32_t b0 = Vs[(ks + t4)     * 72 + an * 8 + g];
                uint32_t b1 = Vs[(ks + t4 + 4) * 72 + an * 8 + g];
                mma_tf32(o[an][0], o[an][1], o[an][2], o[an][3],
                         a0, a1, a2, a3, b0, b1);
            }
        }
    }

    // normalize + store
    float i0 = 1.f / l0, i1 = 1.f / l1;
    float* ob = g_o + (size_t)(b * SEQ + qt * 64) * DMODEL + h * DK;
#pragma unroll
    for (int an = 0; an < 8; an++) {
        int c0 = an * 8 + t4 * 2;
        *(float2*)(ob + (size_t)(rw + g)     * DMODEL + c0) =
            make_float2(o[an][0] * i0, o[an][1] * i0);
        *(float2*)(ob + (size_t)(rw + g + 8) * DMODEL + c0) =
            make_float2(o[an][2] * i1, o[an][3] * i1);
    }
}

// ---------------- launch -----------------------------------------------------
extern "C" void kernel_launch(void* const* d_in, const int* in_sizes, int n_in,
                              void* d_out, int out_size) {
    (void)in_sizes; (void)n_in; (void)out_size;
    const float* x   = (const float*)d_in[0];
    const float* Wq  = (const float*)d_in[1];
    const float* Wk  = (const float*)d_in[2];
    const float* Wv  = (const float*)d_in[3];
    const float* Wo  = (const float*)d_in[4];
    const int*   pos = (const int*)  d_in[5];

    cudaFuncSetAttribute(attn_kernel, cudaFuncAttributeMaxDynamicSharedMemorySize,
                         ATTN_SMEM);

    rope_table_kernel<<<(SEQ * 32 + 255) / 256, 256>>>(pos);

    dim3 gq(DMODEL / 64, MROWS / 128, 3);
    qkv_kernel<<<gq, 256>>>(x, Wq, Wk, Wv);

    dim3 ga(SEQ / 64, NHEAD, BATCH);
    attn_kernel<<<ga, 128, ATTN_SMEM>>>();

    dim3 go(DMODEL / 64, MROWS / 128, 1);
    oproj_kernel<<<go, 256>>>(Wo, (float*)d_out);
}

// round 16
// speedup vs baseline: 2.5471x; 1.1992x over previous
#include <cuda_runtime.h>
#include <math.h>
#include <stdint.h>

#define BATCH  2
#define SEQ    2048
#define DMODEL 1024
#define NHEAD  16
#define DK     64
#define MROWS  (BATCH*SEQ)   // 4096

// ---- tf32 helpers -----------------------------------------------------------
__device__ __forceinline__ uint32_t to_tf32(float f) {
    uint32_t r; asm("cvt.rna.tf32.f32 %0, %1;" : "=r"(r) : "f"(f)); return r;
}
__device__ __forceinline__ void mma_tf32(float& c0, float& c1, float& c2, float& c3,
                                         uint32_t a0, uint32_t a1, uint32_t a2, uint32_t a3,
                                         uint32_t b0, uint32_t b1) {
    asm volatile("mma.sync.aligned.m16n8k8.row.col.f32.tf32.tf32.f32 "
        "{%0,%1,%2,%3}, {%4,%5,%6,%7}, {%8,%9}, {%0,%1,%2,%3};"
        : "+f"(c0), "+f"(c1), "+f"(c2), "+f"(c3)
        : "r"(a0), "r"(a1), "r"(a2), "r"(a3), "r"(b0), "r"(b1));
}

// ---------------- scratch (device globals; no allocations allowed) ----------
__device__ float g_q[(size_t)MROWS * DMODEL];
__device__ float g_k[(size_t)MROWS * DMODEL];
__device__ float g_v[(size_t)MROWS * DMODEL];
__device__ float g_o[(size_t)MROWS * DMODEL];
__device__ float g_cos[SEQ * 32];
__device__ float g_sin[SEQ * 32];

// ---------------- RoPE table -------------------------------------------------
__global__ void rope_table_kernel(const int* __restrict__ pos) {
    int idx = blockIdx.x * blockDim.x + threadIdx.x;
    if (idx >= SEQ * 32) return;
    int sp = idx >> 5;
    int i  = idx & 31;
    float p   = (float)pos[sp];
    float inv = powf(10000.0f, -((float)i) / 32.0f);
    float phi = p * inv;
    g_cos[idx] = cosf(phi);
    g_sin[idx] = sinf(phi);
}

// ---------------- tf32 mma GEMM: BM=128 BN=128 BK=16, warp tile 32x64 --------
// C[m,n] = sum_k A[m,k]*W[n,k] (NT). 8 warps in 4x2; 2-stage double buffer.
// Stride 136 % 32 == 8 -> fragment LDS banks 8*t4+g (all distinct, CF).
__device__ __forceinline__ void gemm_mma_tile(
    const float* __restrict__ A, const float* __restrict__ W,
    float* __restrict__ C, bool rope)
{
    __shared__ uint32_t As[2][16][136];
    __shared__ uint32_t Bs[2][16][136];

    const int tid  = threadIdx.x;
    const int wid  = tid >> 5;
    const int lane = tid & 31;
    const int g    = lane >> 2;
    const int t4   = lane & 3;
    const int bm0  = blockIdx.y * 128;
    const int bn0  = blockIdx.x * 128;
    const int rb   = (wid & 3) * 32;    // warp row base
    const int cb   = (wid >> 2) * 64;   // warp col base

    float c[2][8][4];
#pragma unroll
    for (int i = 0; i < 2; i++)
#pragma unroll
        for (int j = 0; j < 8; j++)
#pragma unroll
            for (int q = 0; q < 4; q++) c[i][j][q] = 0.f;

    // load maps: row = tid&127, k4 = (tid>>7)*4, plus +8 on second 8-col group
    const int r_ld  = tid & 127;
    const int k4_ld = (tid >> 7) << 2;

    const float* Ab = A + (size_t)(bm0 + r_ld) * DMODEL + k4_ld;
    const float* Wb = W + (size_t)(bn0 + r_ld) * DMODEL + k4_ld;

    float4 pa0, pa1, pb0, pb1;

#define GEMM_LDG(s) do { \
        pa0 = *(const float4*)(Ab + (s) * 16); \
        pa1 = *(const float4*)(Ab + (s) * 16 + 8); \
        pb0 = *(const float4*)(Wb + (s) * 16); \
        pb1 = *(const float4*)(Wb + (s) * 16 + 8); \
    } while (0)

#define GEMM_STS(bf) do { \
        As[bf][k4_ld + 0][r_ld] = to_tf32(pa0.x); \
        As[bf][k4_ld + 1][r_ld] = to_tf32(pa0.y); \
        As[bf][k4_ld + 2][r_ld] = to_tf32(pa0.z); \
        As[bf][k4_ld + 3][r_ld] = to_tf32(pa0.w); \
        As[bf][k4_ld + 8][r_ld] = to_tf32(pa1.x); \
        As[bf][k4_ld + 9][r_ld] = to_tf32(pa1.y); \
        As[bf][k4_ld +10][r_ld] = to_tf32(pa1.z); \
        As[bf][k4_ld +11][r_ld] = to_tf32(pa1.w); \
        Bs[bf][k4_ld + 0][r_ld] = to_tf32(pb0.x); \
        Bs[bf][k4_ld + 1][r_ld] = to_tf32(pb0.y); \
        Bs[bf][k4_ld + 2][r_ld] = to_tf32(pb0.z); \
        Bs[bf][k4_ld + 3][r_ld] = to_tf32(pb0.w); \
        Bs[bf][k4_ld + 8][r_ld] = to_tf32(pb1.x); \
        Bs[bf][k4_ld + 9][r_ld] = to_tf32(pb1.y); \
        Bs[bf][k4_ld +10][r_ld] = to_tf32(pb1.z); \
        Bs[bf][k4_ld +11][r_ld] = to_tf32(pb1.w); \
    } while (0)

    GEMM_LDG(0);
    GEMM_STS(0);
    GEMM_LDG(1);

#pragma unroll 1
    for (int s = 0; s < DMODEL / 16; s++) {
        __syncthreads();                 // buf[s&1] ready; other buf free
        const int cur = s & 1;
        if (s + 1 < DMODEL / 16) GEMM_STS(cur ^ 1);
        if (s + 2 < DMODEL / 16) GEMM_LDG(s + 2);

#pragma unroll
        for (int ks = 0; ks < 16; ks += 8) {
            uint32_t a[2][4], bfr[8][2];
#pragma unroll
            for (int am = 0; am < 2; am++) {
                int m = rb + am * 16 + g;
                a[am][0] = As[cur][ks + t4    ][m];
                a[am][1] = As[cur][ks + t4    ][m + 8];
                a[am][2] = As[cur][ks + t4 + 4][m];
                a[am][3] = As[cur][ks + t4 + 4][m + 8];
            }
#pragma unroll
            for (int an = 0; an < 8; an++) {
                int n = cb + an * 8 + g;
                bfr[an][0] = Bs[cur][ks + t4    ][n];
                bfr[an][1] = Bs[cur][ks + t4 + 4][n];
            }
#pragma unroll
            for (int am = 0; am < 2; am++)
#pragma unroll
                for (int an = 0; an < 8; an++)
                    mma_tf32(c[am][an][0], c[am][an][1], c[am][an][2], c[am][an][3],
                             a[am][0], a[am][1], a[am][2], a[am][3],
                             bfr[an][0], bfr[an][1]);
        }
    }
#undef GEMM_LDG
#undef GEMM_STS

    // epilogue with fused RoPE
#pragma unroll
    for (int am = 0; am < 2; am++) {
#pragma unroll
        for (int an = 0; an < 8; an++) {
            int col = bn0 + cb + an * 8 + t4 * 2;
            int r0  = bm0 + rb + am * 16 + g;
            int r1  = r0 + 8;
            float e0 = c[am][an][0], e1 = c[am][an][1];
            float e2 = c[am][an][2], e3 = c[am][an][3];
            if (rope) {
                int i0 = (col & (DK - 1)) >> 1;
                int sp0 = r0 & (SEQ - 1), sp1 = r1 & (SEQ - 1);
                float cc0 = g_cos[sp0 * 32 + i0], ss0 = g_sin[sp0 * 32 + i0];
                float cc1 = g_cos[sp1 * 32 + i0], ss1 = g_sin[sp1 * 32 + i0];
                float x0 = e0, y0 = e1, x1 = e2, y1 = e3;
                e0 = x0 * cc0 - y0 * ss0;  e1 = x0 * ss0 + y0 * cc0;
                e2 = x1 * cc1 - y1 * ss1;  e3 = x1 * ss1 + y1 * cc1;
            }
            *(float2*)(C + (size_t)r0 * DMODEL + col) = make_float2(e0, e1);
            *(float2*)(C + (size_t)r1 * DMODEL + col) = make_float2(e2, e3);
        }
    }
}

__global__ void __launch_bounds__(256) qkv_kernel(
    const float* __restrict__ X,
    const float* __restrict__ Wq, const float* __restrict__ Wk,
    const float* __restrict__ Wv)
{
    const float* W; float* C; bool rope;
    if (blockIdx.z == 0)      { W = Wq; C = g_q; rope = true;  }
    else if (blockIdx.z == 1) { W = Wk; C = g_k; rope = true;  }
    else                      { W = Wv; C = g_v; rope = false; }
    gemm_mma_tile(X, W, C, rope);
}

__global__ void __launch_bounds__(256) oproj_kernel(
    const float* __restrict__ Wo, float* __restrict__ Out)
{
    gemm_mma_tile(g_o, Wo, Out, false);
}

// ---------------- tensor-core causal flash attention (unchanged from R12) ---
#define QS_OFF 0
#define KS_OFF 17408
#define PS_OFF 34816
#define VS_OFF 52224
#define ATTN_SMEM 70656

__global__ void __launch_bounds__(128) attn_kernel() {
    extern __shared__ char smc[];
    uint32_t* Qs = (uint32_t*)(smc + QS_OFF);
    uint32_t* Ks = (uint32_t*)(smc + KS_OFF);
    uint32_t* Ps = (uint32_t*)(smc + PS_OFF);
    uint32_t* Vs = (uint32_t*)(smc + VS_OFF);

    const int tid  = threadIdx.x;
    const int wid  = tid >> 5;
    const int lane = tid & 31;
    const int g    = lane >> 2;
    const int t4   = lane & 3;
    const int qt = blockIdx.x, h = blockIdx.y, b = blockIdx.z;
    const int rw = wid * 16;

    const float* qbase = g_q + (size_t)(b * SEQ + qt * 64) * DMODEL + h * DK;
#pragma unroll
    for (int it = 0; it < 8; it++) {
        int f  = tid + it * 128;
        int r  = f >> 4;
        int d0 = (f & 15) << 2;
        float4 qv = *(const float4*)(qbase + (size_t)r * DMODEL + d0);
        Qs[r * 68 + d0 + 0] = to_tf32(qv.x * 0.125f);
        Qs[r * 68 + d0 + 1] = to_tf32(qv.y * 0.125f);
        Qs[r * 68 + d0 + 2] = to_tf32(qv.z * 0.125f);
        Qs[r * 68 + d0 + 3] = to_tf32(qv.w * 0.125f);
    }

    float m0 = -1e30f, m1 = -1e30f, l0 = 0.f, l1 = 0.f;
    float o[8][4];
#pragma unroll
    for (int an = 0; an < 8; an++)
#pragma unroll
        for (int q = 0; q < 4; q++) o[an][q] = 0.f;

    const float* kbase = g_k + (size_t)(b * SEQ) * DMODEL + h * DK;
    const float* vbase = g_v + (size_t)(b * SEQ) * DMODEL + h * DK;

#pragma unroll 1
    for (int kt = 0; kt <= qt; kt++) {
        __syncthreads();

#pragma unroll
        for (int it = 0; it < 8; it++) {
            int f  = tid + it * 128;
            int j  = f >> 4;
            int d0 = (f & 15) << 2;
            const float* kr = kbase + (size_t)(kt * 64 + j) * DMODEL + d0;
            float4 kv = *(const float4*)kr;
            Ks[j * 68 + d0 + 0] = to_tf32(kv.x);
            Ks[j * 68 + d0 + 1] = to_tf32(kv.y);
            Ks[j * 68 + d0 + 2] = to_tf32(kv.z);
            Ks[j * 68 + d0 + 3] = to_tf32(kv.w);
            const float* vr = vbase + (size_t)(kt * 64 + j) * DMODEL + d0;
            float4 vv = *(const float4*)vr;
            Vs[j * 72 + d0 + 0] = to_tf32(vv.x);
            Vs[j * 72 + d0 + 1] = to_tf32(vv.y);
            Vs[j * 72 + d0 + 2] = to_tf32(vv.z);
            Vs[j * 72 + d0 + 3] = to_tf32(vv.w);
        }
        __syncthreads();

        float sc[8][4];
#pragma unroll
        for (int an = 0; an < 8; an++)
#pragma unroll
            for (int q = 0; q < 4; q++) sc[an][q] = 0.f;
#pragma unroll
        for (int ks = 0; ks < 64; ks += 8) {
            uint32_t a0 = Qs[(rw + g)     * 68 + ks + t4];
            uint32_t a1 = Qs[(rw + g + 8) * 68 + ks + t4];
            uint32_t a2 = Qs[(rw + g)     * 68 + ks + t4 + 4];
            uint32_t a3 = Qs[(rw + g + 8) * 68 + ks + t4 + 4];
#pragma unroll
            for (int an = 0; an < 8; an++) {
                uint32_t b0 = Ks[(an * 8 + g) * 68 + ks + t4];
                uint32_t b1 = Ks[(an * 8 + g) * 68 + ks + t4 + 4];
                mma_tf32(sc[an][0], sc[an][1], sc[an][2], sc[an][3],
                         a0, a1, a2, a3, b0, b1);
            }
        }

        if (kt == qt) {
            int q0 = rw + g, q1 = q0 + 8;
#pragma unroll
            for (int an = 0; an < 8; an++) {
                int c0 = an * 8 + t4 * 2;
                if (c0     > q0) sc[an][0] = -1e30f;
                if (c0 + 1 > q0) sc[an][1] = -1e30f;
                if (c0     > q1) sc[an][2] = -1e30f;
                if (c0 + 1 > q1) sc[an][3] = -1e30f;
            }
        }

        float mx0 = -1e30f, mx1 = -1e30f;
#pragma unroll
        for (int an = 0; an < 8; an++) {
            mx0 = fmaxf(mx0, fmaxf(sc[an][0], sc[an][1]));
            mx1 = fmaxf(mx1, fmaxf(sc[an][2], sc[an][3]));
        }
        mx0 = fmaxf(mx0, __shfl_xor_sync(0xffffffffu, mx0, 1));
        mx0 = fmaxf(mx0, __shfl_xor_sync(0xffffffffu, mx0, 2));
        mx1 = fmaxf(mx1, __shfl_xor_sync(0xffffffffu, mx1, 1));
        mx1 = fmaxf(mx1, __shfl_xor_sync(0xffffffffu, mx1, 2));
        float nm0 = fmaxf(m0, mx0), nm1 = fmaxf(m1, mx1);
        float al0 = __expf(m0 - nm0), al1 = __expf(m1 - nm1);
        m0 = nm0; m1 = nm1;

        float sum0 = 0.f, sum1 = 0.f;
#pragma unroll
        for (int an = 0; an < 8; an++) {
            float p0 = __expf(sc[an][0] - nm0);
            float p1 = __expf(sc[an][1] - nm0);
            float p2 = __expf(sc[an][2] - nm1);
            float p3 = __expf(sc[an][3] - nm1);
            sum0 += p0 + p1;
            sum1 += p2 + p3;
            int c0 = an * 8 + t4 * 2;
            Ps[(rw + g)     * 68 + c0    ] = to_tf32(p0);
            Ps[(rw + g)     * 68 + c0 + 1] = to_tf32(p1);
            Ps[(rw + g + 8) * 68 + c0    ] = to_tf32(p2);
            Ps[(rw + g + 8) * 68 + c0 + 1] = to_tf32(p3);
        }
        sum0 += __shfl_xor_sync(0xffffffffu, sum0, 1);
        sum0 += __shfl_xor_sync(0xffffffffu, sum0, 2);
        sum1 += __shfl_xor_sync(0xffffffffu, sum1, 1);
        sum1 += __shfl_xor_sync(0xffffffffu, sum1, 2);
        l0 = l0 * al0 + sum0;
        l1 = l1 * al1 + sum1;

#pragma unroll
        for (int an = 0; an < 8; an++) {
            o[an][0] *= al0; o[an][1] *= al0;
            o[an][2] *= al1; o[an][3] *= al1;
        }

        __syncthreads();

#pragma unroll
        for (int ks = 0; ks < 64; ks += 8) {
            uint32_t a0 = Ps[(rw + g)     * 68 + ks + t4];
            uint32_t a1 = Ps[(rw + g + 8) * 68 + ks + t4];
            uint32_t a2 = Ps[(rw + g)     * 68 + ks + t4 + 4];
            uint32_t a3 = Ps[(rw + g + 8) * 68 + ks + t4 + 4];
#pragma unroll
            for (int an = 0; an < 8; an++) {
                uint32_t b0 = Vs[(ks + t4)     * 72 + an * 8 + g];
                uint32_t b1 = Vs[(ks + t4 + 4) * 72 + an * 8 + g];
                mma_tf32(o[an][0], o[an][1], o[an][2], o[an][3],
                         a0, a1, a2, a3, b0, b1);
            }
        }
    }

    float i0 = 1.f / l0, i1 = 1.f / l1;
    float* ob = g_o + (size_t)(b * SEQ + qt * 64) * DMODEL + h * DK;
#pragma unroll
    for (int an = 0; an < 8; an++) {
        int c0 = an * 8 + t4 * 2;
        *(float2*)(ob + (size_t)(rw + g)     * DMODEL + c0) =
            make_float2(o[an][0] * i0, o[an][1] * i0);
        *(float2*)(ob + (size_t)(rw + g + 8) * DMODEL + c0) =
            make_float2(o[an][2] * i1, o[an][3] * i1);
    }
}

// ---------------- launch -----------------------------------------------------
extern "C" void kernel_launch(void* const* d_in, const int* in_sizes, int n_in,
                              void* d_out, int out_size) {
    (void)in_sizes; (void)n_in; (void)out_size;
    const float* x   = (const float*)d_in[0];
    const float* Wq  = (const float*)d_in[1];
    const float* Wk  = (const float*)d_in[2];
    const float* Wv  = (const float*)d_in[3];
    const float* Wo  = (const float*)d_in[4];
    const int*   pos = (const int*)  d_in[5];

    cudaFuncSetAttribute(attn_kernel, cudaFuncAttributeMaxDynamicSharedMemorySize,
                         ATTN_SMEM);

    rope_table_kernel<<<(SEQ * 32 + 255) / 256, 256>>>(pos);

    dim3 gq(DMODEL / 128, MROWS / 128, 3);
    qkv_kernel<<<gq, 256>>>(x, Wq, Wk, Wv);

    dim3 ga(SEQ / 64, NHEAD, BATCH);
    attn_kernel<<<ga, 128, ATTN_SMEM>>>();

    dim3 go(DMODEL / 128, MROWS / 128, 1);
    oproj_kernel<<<go, 256>>>(Wo, (float*)d_out);
}

// round 17
// speedup vs baseline: 2.9647x; 1.1639x over previous
#include <cuda_runtime.h>
#include <math.h>
#include <stdint.h>

#define BATCH  2
#define SEQ    2048
#define DMODEL 1024
#define NHEAD  16
#define DK     64
#define MROWS  (BATCH*SEQ)   // 4096

// ---- tf32 helpers -----------------------------------------------------------
__device__ __forceinline__ uint32_t to_tf32(float f) {
    uint32_t r; asm("cvt.rna.tf32.f32 %0, %1;" : "=r"(r) : "f"(f)); return r;
}
__device__ __forceinline__ void mma_tf32(float& c0, float& c1, float& c2, float& c3,
                                         uint32_t a0, uint32_t a1, uint32_t a2, uint32_t a3,
                                         uint32_t b0, uint32_t b1) {
    asm volatile("mma.sync.aligned.m16n8k8.row.col.f32.tf32.tf32.f32 "
        "{%0,%1,%2,%3}, {%4,%5,%6,%7}, {%8,%9}, {%0,%1,%2,%3};"
        : "+f"(c0), "+f"(c1), "+f"(c2), "+f"(c3)
        : "r"(a0), "r"(a1), "r"(a2), "r"(a3), "r"(b0), "r"(b1));
}
__device__ __forceinline__ uint32_t smem_u32(const void* p) {
    uint32_t a;
    asm("{ .reg .u64 t; cvta.to.shared.u64 t, %1; cvt.u32.u64 %0, t; }" : "=r"(a) : "l"(p));
    return a;
}
__device__ __forceinline__ void cp16(uint32_t dst, const void* src) {
    asm volatile("cp.async.cg.shared.global [%0], [%1], 16;" :: "r"(dst), "l"(src));
}
#define CP_COMMIT() asm volatile("cp.async.commit_group;" ::: "memory")
#define CP_WAIT2()  asm volatile("cp.async.wait_group 2;" ::: "memory")

// ---------------- scratch (device globals; no allocations allowed) ----------
__device__ float g_q[(size_t)MROWS * DMODEL];
__device__ float g_k[(size_t)MROWS * DMODEL];
__device__ float g_v[(size_t)MROWS * DMODEL];
__device__ float g_o[(size_t)MROWS * DMODEL];     // attn out, tf32-rounded at store
__device__ float g_x[(size_t)MROWS * DMODEL];     // tf32-rounded input X
__device__ float g_wq[(size_t)DMODEL * DMODEL];   // tf32-rounded weights
__device__ float g_wk[(size_t)DMODEL * DMODEL];
__device__ float g_wv[(size_t)DMODEL * DMODEL];
__device__ float g_wo[(size_t)DMODEL * DMODEL];
__device__ float g_cos[SEQ * 32];
__device__ float g_sin[SEQ * 32];

// ---------------- pre-round pass (fp32 -> tf32-rounded fp32) -----------------
__global__ void round4_kernel(const float4* __restrict__ src, float4* __restrict__ dst,
                              int n4) {
    int i = blockIdx.x * blockDim.x + threadIdx.x;
    if (i >= n4) return;
    float4 v = src[i];
    v.x = __uint_as_float(to_tf32(v.x));
    v.y = __uint_as_float(to_tf32(v.y));
    v.z = __uint_as_float(to_tf32(v.z));
    v.w = __uint_as_float(to_tf32(v.w));
    dst[i] = v;
}

// ---------------- RoPE table -------------------------------------------------
__global__ void rope_table_kernel(const int* __restrict__ pos) {
    int idx = blockIdx.x * blockDim.x + threadIdx.x;
    if (idx >= SEQ * 32) return;
    int sp = idx >> 5;
    int i  = idx & 31;
    float p   = (float)pos[sp];
    float inv = powf(10000.0f, -((float)i) / 32.0f);
    float phi = p * inv;
    g_cos[idx] = cosf(phi);
    g_sin[idx] = sinf(phi);
}

// ---------------- tf32 mma GEMM, cp.async 4-stage pipeline -------------------
// C[m,n] = sum_k A[m,k]*W[n,k] (NT); inputs MUST be tf32-pre-rounded.
// BM=BN=128, BK=16; 8 warps 4x2, warp tile 32x64.
// smem [row][k] stride 20 floats (80B): 20g+t4 mod 32 hits all 32 banks -> CF
// fragment loads; cp.async dst 64B/row contiguous, 16B aligned.
#define KSTRIDE      20
#define STAGE_FLOATS (2 * 128 * KSTRIDE)        // A block + B block = 5120
#define STAGE_BYTES  (STAGE_FLOATS * 4)         // 20480
#define GEMM_SMEM_DYN (4 * STAGE_BYTES)         // 81920

__device__ __forceinline__ void gemm_cp_tile(
    const float* __restrict__ A, const float* __restrict__ W,
    float* __restrict__ C, bool rope)
{
    extern __shared__ float sm[];
    const uint32_t sbase = smem_u32(sm);

    const int tid  = threadIdx.x;
    const int wid  = tid >> 5;
    const int lane = tid & 31;
    const int g    = lane >> 2;
    const int t4   = lane & 3;
    const int bm0  = blockIdx.y * 128;
    const int bn0  = blockIdx.x * 128;
    const int rb   = (wid & 3) * 32;    // warp row base
    const int cb   = (wid >> 2) * 64;   // warp col base

    float c[2][8][4];
#pragma unroll
    for (int i = 0; i < 2; i++)
#pragma unroll
        for (int j = 0; j < 8; j++)
#pragma unroll
            for (int q = 0; q < 4; q++) c[i][j][q] = 0.f;

    // loader: threads 0-127 -> A rows, 128-255 -> B rows; 64B (=BK) per row/stage
    const int  lrow = tid & 127;
    const bool isB  = tid >= 128;
    const float* gsrc = isB ? (W + (size_t)(bn0 + lrow) * DMODEL)
                            : (A + (size_t)(bm0 + lrow) * DMODEL);
    const uint32_t sdst0 = sbase + (isB ? (uint32_t)(128 * KSTRIDE * 4) : 0u)
                         + (uint32_t)(lrow * KSTRIDE * 4);

#define GEMM_ISSUE(s) do { \
        uint32_t _d = sdst0 + (uint32_t)(((s) & 3) * STAGE_BYTES); \
        const float* _s = gsrc + (s) * 16; \
        cp16(_d,      _s);      cp16(_d + 16, _s + 4); \
        cp16(_d + 32, _s + 8);  cp16(_d + 48, _s + 12); \
    } while (0)

    GEMM_ISSUE(0); CP_COMMIT();
    GEMM_ISSUE(1); CP_COMMIT();
    GEMM_ISSUE(2); CP_COMMIT();

#pragma unroll 1
    for (int s = 0; s < DMODEL / 16; s++) {
        CP_WAIT2();                      // stage s landed
        __syncthreads();                 // visible block-wide; buf (s+3)&3 free
        if (s + 3 < DMODEL / 16) GEMM_ISSUE(s + 3);
        CP_COMMIT();                     // empty group near tail keeps count exact

        const uint32_t* Asu = (const uint32_t*)(sm + (s & 3) * STAGE_FLOATS);
        const uint32_t* Bsu = Asu + 128 * KSTRIDE;

#pragma unroll
        for (int ks = 0; ks < 16; ks += 8) {
            uint32_t a[2][4], bfr[8][2];
#pragma unroll
            for (int am = 0; am < 2; am++) {
                int m = rb + am * 16 + g;
                a[am][0] = Asu[(m)     * KSTRIDE + ks + t4];
                a[am][1] = Asu[(m + 8) * KSTRIDE + ks + t4];
                a[am][2] = Asu[(m)     * KSTRIDE + ks + t4 + 4];
                a[am][3] = Asu[(m + 8) * KSTRIDE + ks + t4 + 4];
            }
#pragma unroll
            for (int an = 0; an < 8; an++) {
                int n = cb + an * 8 + g;
                bfr[an][0] = Bsu[n * KSTRIDE + ks + t4];
                bfr[an][1] = Bsu[n * KSTRIDE + ks + t4 + 4];
            }
#pragma unroll
            for (int am = 0; am < 2; am++)
#pragma unroll
                for (int an = 0; an < 8; an++)
                    mma_tf32(c[am][an][0], c[am][an][1], c[am][an][2], c[am][an][3],
                             a[am][0], a[am][1], a[am][2], a[am][3],
                             bfr[an][0], bfr[an][1]);
        }
    }
#undef GEMM_ISSUE

    // epilogue with fused RoPE
#pragma unroll
    for (int am = 0; am < 2; am++) {
#pragma unroll
        for (int an = 0; an < 8; an++) {
            int col = bn0 + cb + an * 8 + t4 * 2;
            int r0  = bm0 + rb + am * 16 + g;
            int r1  = r0 + 8;
            float e0 = c[am][an][0], e1 = c[am][an][1];
            float e2 = c[am][an][2], e3 = c[am][an][3];
            if (rope) {
                int i0 = (col & (DK - 1)) >> 1;
                int sp0 = r0 & (SEQ - 1), sp1 = r1 & (SEQ - 1);
                float cc0 = g_cos[sp0 * 32 + i0], ss0 = g_sin[sp0 * 32 + i0];
                float cc1 = g_cos[sp1 * 32 + i0], ss1 = g_sin[sp1 * 32 + i0];
                float x0 = e0, y0 = e1, x1 = e2, y1 = e3;
                e0 = x0 * cc0 - y0 * ss0;  e1 = x0 * ss0 + y0 * cc0;
                e2 = x1 * cc1 - y1 * ss1;  e3 = x1 * ss1 + y1 * cc1;
            }
            *(float2*)(C + (size_t)r0 * DMODEL + col) = make_float2(e0, e1);
            *(float2*)(C + (size_t)r1 * DMODEL + col) = make_float2(e2, e3);
        }
    }
}

__global__ void __launch_bounds__(256) qkv_kernel() {
    const float* W; float* C; bool rope;
    if (blockIdx.z == 0)      { W = g_wq; C = g_q; rope = true;  }
    else if (blockIdx.z == 1) { W = g_wk; C = g_k; rope = true;  }
    else                      { W = g_wv; C = g_v; rope = false; }
    gemm_cp_tile(g_x, W, C, rope);
}

__global__ void __launch_bounds__(256) oproj_kernel(float* __restrict__ Out) {
    gemm_cp_tile(g_o, g_wo, Out, false);
}

// ---------------- tensor-core causal flash attention -------------------------
// (R12 design; output store tf32-rounded so oproj can cp.async raw)
#define QS_OFF 0
#define KS_OFF 17408
#define PS_OFF 34816
#define VS_OFF 52224
#define ATTN_SMEM 70656

__global__ void __launch_bounds__(128) attn_kernel() {
    extern __shared__ char smc[];
    uint32_t* Qs = (uint32_t*)(smc + QS_OFF);
    uint32_t* Ks = (uint32_t*)(smc + KS_OFF);
    uint32_t* Ps = (uint32_t*)(smc + PS_OFF);
    uint32_t* Vs = (uint32_t*)(smc + VS_OFF);

    const int tid  = threadIdx.x;
    const int wid  = tid >> 5;
    const int lane = tid & 31;
    const int g    = lane >> 2;
    const int t4   = lane & 3;
    const int qt = blockIdx.x, h = blockIdx.y, b = blockIdx.z;
    const int rw = wid * 16;

    const float* qbase = g_q + (size_t)(b * SEQ + qt * 64) * DMODEL + h * DK;
#pragma unroll
    for (int it = 0; it < 8; it++) {
        int f  = tid + it * 128;
        int r  = f >> 4;
        int d0 = (f & 15) << 2;
        float4 qv = *(const float4*)(qbase + (size_t)r * DMODEL + d0);
        Qs[r * 68 + d0 + 0] = to_tf32(qv.x * 0.125f);
        Qs[r * 68 + d0 + 1] = to_tf32(qv.y * 0.125f);
        Qs[r * 68 + d0 + 2] = to_tf32(qv.z * 0.125f);
        Qs[r * 68 + d0 + 3] = to_tf32(qv.w * 0.125f);
    }

    float m0 = -1e30f, m1 = -1e30f, l0 = 0.f, l1 = 0.f;
    float o[8][4];
#pragma unroll
    for (int an = 0; an < 8; an++)
#pragma unroll
        for (int q = 0; q < 4; q++) o[an][q] = 0.f;

    const float* kbase = g_k + (size_t)(b * SEQ) * DMODEL + h * DK;
    const float* vbase = g_v + (size_t)(b * SEQ) * DMODEL + h * DK;

#pragma unroll 1
    for (int kt = 0; kt <= qt; kt++) {
        __syncthreads();

#pragma unroll
        for (int it = 0; it < 8; it++) {
            int f  = tid + it * 128;
            int j  = f >> 4;
            int d0 = (f & 15) << 2;
            const float* kr = kbase + (size_t)(kt * 64 + j) * DMODEL + d0;
            float4 kv = *(const float4*)kr;
            Ks[j * 68 + d0 + 0] = to_tf32(kv.x);
            Ks[j * 68 + d0 + 1] = to_tf32(kv.y);
            Ks[j * 68 + d0 + 2] = to_tf32(kv.z);
            Ks[j * 68 + d0 + 3] = to_tf32(kv.w);
            const float* vr = vbase + (size_t)(kt * 64 + j) * DMODEL + d0;
            float4 vv = *(const float4*)vr;
            Vs[j * 72 + d0 + 0] = to_tf32(vv.x);
            Vs[j * 72 + d0 + 1] = to_tf32(vv.y);
            Vs[j * 72 + d0 + 2] = to_tf32(vv.z);
            Vs[j * 72 + d0 + 3] = to_tf32(vv.w);
        }
        __syncthreads();

        float sc[8][4];
#pragma unroll
        for (int an = 0; an < 8; an++)
#pragma unroll
            for (int q = 0; q < 4; q++) sc[an][q] = 0.f;
#pragma unroll
        for (int ks = 0; ks < 64; ks += 8) {
            uint32_t a0 = Qs[(rw + g)     * 68 + ks + t4];
            uint32_t a1 = Qs[(rw + g + 8) * 68 + ks + t4];
            uint32_t a2 = Qs[(rw + g)     * 68 + ks + t4 + 4];
            uint32_t a3 = Qs[(rw + g + 8) * 68 + ks + t4 + 4];
#pragma unroll
            for (int an = 0; an < 8; an++) {
                uint32_t b0 = Ks[(an * 8 + g) * 68 + ks + t4];
                uint32_t b1 = Ks[(an * 8 + g) * 68 + ks + t4 + 4];
                mma_tf32(sc[an][0], sc[an][1], sc[an][2], sc[an][3],
                         a0, a1, a2, a3, b0, b1);
            }
        }

        if (kt == qt) {
            int q0 = rw + g, q1 = q0 + 8;
#pragma unroll
            for (int an = 0; an < 8; an++) {
                int c0 = an * 8 + t4 * 2;
                if (c0     > q0) sc[an][0] = -1e30f;
                if (c0 + 1 > q0) sc[an][1] = -1e30f;
                if (c0     > q1) sc[an][2] = -1e30f;
                if (c0 + 1 > q1) sc[an][3] = -1e30f;
            }
        }

        float mx0 = -1e30f, mx1 = -1e30f;
#pragma unroll
        for (int an = 0; an < 8; an++) {
            mx0 = fmaxf(mx0, fmaxf(sc[an][0], sc[an][1]));
            mx1 = fmaxf(mx1, fmaxf(sc[an][2], sc[an][3]));
        }
        mx0 = fmaxf(mx0, __shfl_xor_sync(0xffffffffu, mx0, 1));
        mx0 = fmaxf(mx0, __shfl_xor_sync(0xffffffffu, mx0, 2));
        mx1 = fmaxf(mx1, __shfl_xor_sync(0xffffffffu, mx1, 1));
        mx1 = fmaxf(mx1, __shfl_xor_sync(0xffffffffu, mx1, 2));
        float nm0 = fmaxf(m0, mx0), nm1 = fmaxf(m1, mx1);
        float al0 = __expf(m0 - nm0), al1 = __expf(m1 - nm1);
        m0 = nm0; m1 = nm1;

        float sum0 = 0.f, sum1 = 0.f;
#pragma unroll
        for (int an = 0; an < 8; an++) {
            float p0 = __expf(sc[an][0] - nm0);
            float p1 = __expf(sc[an][1] - nm0);
            float p2 = __expf(sc[an][2] - nm1);
            float p3 = __expf(sc[an][3] - nm1);
            sum0 += p0 + p1;
            sum1 += p2 + p3;
            int c0 = an * 8 + t4 * 2;
            Ps[(rw + g)     * 68 + c0    ] = to_tf32(p0);
            Ps[(rw + g)     * 68 + c0 + 1] = to_tf32(p1);
            Ps[(rw + g + 8) * 68 + c0    ] = to_tf32(p2);
            Ps[(rw + g + 8) * 68 + c0 + 1] = to_tf32(p3);
        }
        sum0 += __shfl_xor_sync(0xffffffffu, sum0, 1);
        sum0 += __shfl_xor_sync(0xffffffffu, sum0, 2);
        sum1 += __shfl_xor_sync(0xffffffffu, sum1, 1);
        sum1 += __shfl_xor_sync(0xffffffffu, sum1, 2);
        l0 = l0 * al0 + sum0;
        l1 = l1 * al1 + sum1;

#pragma unroll
        for (int an = 0; an < 8; an++) {
            o[an][0] *= al0; o[an][1] *= al0;
            o[an][2] *= al1; o[an][3] *= al1;
        }

        __syncthreads();

#pragma unroll
        for (int ks = 0; ks < 64; ks += 8) {
            uint32_t a0 = Ps[(rw + g)     * 68 + ks + t4];
            uint32_t a1 = Ps[(rw + g + 8) * 68 + ks + t4];
            uint32_t a2 = Ps[(rw + g)     * 68 + ks + t4 + 4];
            uint32_t a3 = Ps[(rw + g + 8) * 68 + ks + t4 + 4];
#pragma unroll
            for (int an = 0; an < 8; an++) {
                uint32_t b0 = Vs[(ks + t4)     * 72 + an * 8 + g];
                uint32_t b1 = Vs[(ks + t4 + 4) * 72 + an * 8 + g];
                mma_tf32(o[an][0], o[an][1], o[an][2], o[an][3],
                         a0, a1, a2, a3, b0, b1);
            }
        }
    }

    // normalize + store, tf32-rounded (feeds cp.async oproj with exact bits)
    float i0 = 1.f / l0, i1 = 1.f / l1;
    float* ob = g_o + (size_t)(b * SEQ + qt * 64) * DMODEL + h * DK;
#pragma unroll
    for (int an = 0; an < 8; an++) {
        int c0 = an * 8 + t4 * 2;
        *(float2*)(ob + (size_t)(rw + g) * DMODEL + c0) = make_float2(
            __uint_as_float(to_tf32(o[an][0] * i0)),
            __uint_as_float(to_tf32(o[an][1] * i0)));
        *(float2*)(ob + (size_t)(rw + g + 8) * DMODEL + c0) = make_float2(
            __uint_as_float(to_tf32(o[an][2] * i1)),
            __uint_as_float(to_tf32(o[an][3] * i1)));
    }
}

// ---------------- launch -----------------------------------------------------
extern "C" void kernel_launch(void* const* d_in, const int* in_sizes, int n_in,
                              void* d_out, int out_size) {
    (void)in_sizes; (void)n_in; (void)out_size;
    const float* x   = (const float*)d_in[0];
    const float* Wq  = (const float*)d_in[1];
    const float* Wk  = (const float*)d_in[2];
    const float* Wv  = (const float*)d_in[3];
    const float* Wo  = (const float*)d_in[4];
    const int*   pos = (const int*)  d_in[5];

    cudaFuncSetAttribute(attn_kernel, cudaFuncAttributeMaxDynamicSharedMemorySize,
                         ATTN_SMEM);
    cudaFuncSetAttribute(qkv_kernel, cudaFuncAttributeMaxDynamicSharedMemorySize,
                         GEMM_SMEM_DYN);
    cudaFuncSetAttribute(oproj_kernel, cudaFuncAttributeMaxDynamicSharedMemorySize,
                         GEMM_SMEM_DYN);

    rope_table_kernel<<<(SEQ * 32 + 255) / 256, 256>>>(pos);

    // pre-round all GEMM inputs to tf32 (idempotent, bit-exact vs R16 path)
    float *gx, *gwq, *gwk, *gwv, *gwo;
    cudaGetSymbolAddress((void**)&gx,  g_x);
    cudaGetSymbolAddress((void**)&gwq, g_wq);
    cudaGetSymbolAddress((void**)&gwk, g_wk);
    cudaGetSymbolAddress((void**)&gwv, g_wv);
    cudaGetSymbolAddress((void**)&gwo, g_wo);
    const int nX4 = MROWS * DMODEL / 4;       // 1,048,576
    const int nW4 = DMODEL * DMODEL / 4;      // 262,144
    round4_kernel<<<(nX4 + 255) / 256, 256>>>((const float4*)x,  (float4*)gx,  nX4);
    round4_kernel<<<(nW4 + 255) / 256, 256>>>((const float4*)Wq, (float4*)gwq, nW4);
    round4_kernel<<<(nW4 + 255) / 256, 256>>>((const float4*)Wk, (float4*)gwk, nW4);
    round4_kernel<<<(nW4 + 255) / 256, 256>>>((const float4*)Wv, (float4*)gwv, nW4);
    round4_kernel<<<(nW4 + 255) / 256, 256>>>((const float4*)Wo, (float4*)gwo, nW4);

    dim3 gq(DMODEL / 128, MROWS / 128, 3);
    qkv_kernel<<<gq, 256, GEMM_SMEM_DYN>>>();

    dim3 ga(SEQ / 64, NHEAD, BATCH);
    attn_kernel<<<ga, 128, ATTN_SMEM>>>();

    dim3 go(DMODEL / 128, MROWS / 128, 1);
    oproj_kernel<<<go, 256, GEMM_SMEM_DYN>>>((float*)d_out);
}